// round 16
// baseline (speedup 1.0000x reference)
#include <cuda_runtime.h>
#include <cuda_fp16.h>
#include <cstdint>
#include <cstddef>

// ---------------- problem constants ----------------
#define TNUM   8192
#define DIMD   2560
#define INTERD 1664
#define NEXP   16
#define TOPK   6
#define NPAIR  (TNUM * TOPK)          // 49152
#define MAXROWS 51200                 // >= 49152 + 16*127, multiple of 128
#define MAXTILES 400                  // 128-row tiles
#define KC 64                         // K elems per chunk (64 fp16 = 128B = SW128 atom row)
#define NK1 (DIMD / KC)               // 40
#define NK2 (INTERD / KC)             // 26
#define NT1 (INTERD / 128)            // 13  (N tiles of 128)
#define NP2 10                        // 20/2 ntile-pairs for GEMM2
#define NSM 148

// idesc kind::f16 (fp16 in, fp32 acc): dtype=F32(1<<4), atype=F16(0), btype=F16(0),
// N=128 -> 16<<17, M=128 -> 8<<24
#define IDESC128 0x08200010u

// Both GEMMs: 2 stages x (3 buffers x 16KB) = 48KB/stage -> 2 CTAs/SM
#define STAGEB 49152u

// Feature gate: tcgen05 is sm_103a-specific; base-family passes get a compile-only fallback.
#if defined(__CUDA_ARCH_FEAT_SM103_ALL) || (defined(__CUDA_ARCH_SPECIFIC__) && (__CUDA_ARCH_SPECIFIC__ == 1030))
#define HAS_TC5 1
#else
#define HAS_TC5 0
#endif

// ---------------- device scratch (static) ----------------
__device__ __half g_xh [(size_t)TNUM * DIMD];
__device__ __half g_w1h[(size_t)NEXP * INTERD * DIMD];
__device__ __half g_w3h[(size_t)NEXP * INTERD * DIMD];
__device__ __half g_w2h[(size_t)NEXP * DIMD * INTERD];
__device__ __half g_hbuf[(size_t)MAXROWS * INTERD];
__device__ int     g_cnt[NEXP];
__device__ int     g_rank[NPAIR];
__device__ uint8_t g_eid[NPAIR];
__device__ int   g_pairtok[MAXROWS];
__device__ float g_pairw[MAXROWS];
__device__ int   g_tile_e[MAXTILES];
__device__ int   g_tile_r0[MAXTILES];
__device__ int   g_ntiles;
__device__ int   g_is64;

// ---------------- generic helpers ----------------
__device__ __forceinline__ uint32_t smem_u32(const void* p) {
    uint32_t a;
    asm("{ .reg .u64 t; cvta.to.shared.u64 t, %1; cvt.u32.u64 %0, t; }" : "=r"(a) : "l"(p));
    return a;
}
__device__ __forceinline__ uint32_t elect1() {
    uint32_t p;
    asm volatile("{\n\t.reg .pred p;\n\telect.sync _|p, 0xFFFFFFFF;\n\tselp.b32 %0, 1, 0, p;\n\t}"
                 : "=r"(p));
    return p;
}
#define SWZ(off) ((off) ^ (((off) >> 3) & 0x70u))

__device__ __forceinline__ void mbar_init(uint32_t a, uint32_t c) {
    asm volatile("mbarrier.init.shared.b64 [%0], %1;" :: "r"(a), "r"(c) : "memory");
}
__device__ __forceinline__ void mbar_wait(uint32_t a, uint32_t parity) {
    asm volatile(
        "{\n\t.reg .pred P;\n\t"
        "W_%=:\n\t"
        "mbarrier.try_wait.parity.acquire.cta.shared::cta.b64 P, [%0], %1, 0x989680;\n\t"
        "@P bra.uni D_%=;\n\t"
        "bra.uni W_%=;\n\t"
        "D_%=:\n\t}"
        :: "r"(a), "r"(parity) : "memory");
}
// .cg: bypass L1 (A tiles, no cross-CTA reuse)
__device__ __forceinline__ void cpa16(uint32_t dst, const void* src) {
    asm volatile("cp.async.cg.shared.global [%0], [%1], 16;" :: "r"(dst), "l"(src) : "memory");
}
// .ca: allocate in L1 (B panels: co-resident CTA computes the same panel)
__device__ __forceinline__ void cpa16ca(uint32_t dst, const void* src) {
    asm volatile("cp.async.ca.shared.global [%0], [%1], 16;" :: "r"(dst), "l"(src) : "memory");
}
__device__ __forceinline__ void cpa_commit() {
    asm volatile("cp.async.commit_group;" ::: "memory");
}
#define CPA_WAIT1() asm volatile("cp.async.wait_group 1;" ::: "memory")
#define FENCE_ASYNC() asm volatile("fence.proxy.async.shared::cta;" ::: "memory")

// SW128 K-major descriptor: layout=2, version=1, SBO=64, LBO=1
#define DESC_BASE ((uint64_t(2) << 61) | (uint64_t(1) << 46) | (uint64_t(64) << 32) | (uint64_t(1) << 16))
#define MKDESC(addr) (DESC_BASE | ((uint64_t)((addr) >> 4) & 0x3FFFull))

#if HAS_TC5
// ---------------- tcgen05 helpers (sm_103a-specific pass only) ----------------
__device__ __forceinline__ void tc_alloc(uint32_t smem_dst, uint32_t ncols) {
    asm volatile("tcgen05.alloc.cta_group::1.sync.aligned.shared::cta.b32 [%0], %1;"
                 :: "r"(smem_dst), "r"(ncols) : "memory");
}
__device__ __forceinline__ void tc_relinq() {
    asm volatile("tcgen05.relinquish_alloc_permit.cta_group::1.sync.aligned;");
}
__device__ __forceinline__ void tc_dealloc(uint32_t tmem, uint32_t ncols) {
    asm volatile("tcgen05.dealloc.cta_group::1.sync.aligned.b32 %0, %1;" :: "r"(tmem), "r"(ncols));
}
__device__ __forceinline__ void tc_commit(uint32_t mbar) {
    asm volatile("tcgen05.commit.cta_group::1.mbarrier::arrive::one.shared::cluster.b64 [%0];"
                 :: "r"(mbar) : "memory");
}
__device__ __forceinline__ void tc_fence_after() {
    asm volatile("tcgen05.fence::after_thread_sync;" ::: "memory");
}
__device__ __forceinline__ void tc_fence_before() {
    asm volatile("tcgen05.fence::before_thread_sync;" ::: "memory");
}
__device__ __forceinline__ void tc_wait_ld() {
    asm volatile("tcgen05.wait::ld.sync.aligned;" ::: "memory");
}
__device__ __forceinline__ void mma_f16_ss(uint32_t d, uint64_t a, uint64_t b,
                                           uint32_t idesc, uint32_t acc) {
    asm volatile(
        "{\n\t.reg .pred p;\n\tsetp.ne.u32 p, %4, 0;\n\t"
        "tcgen05.mma.cta_group::1.kind::f16 [%0], %1, %2, %3, {%5,%5,%5,%5}, p;\n\t}"
        :: "r"(d), "l"(a), "l"(b), "r"(idesc), "r"(acc), "r"(0u) : "memory");
}
#define LDTM32(r, tmem_addr) \
    asm volatile( \
        "tcgen05.ld.sync.aligned.32x32b.x32.b32 " \
        "{%0, %1, %2, %3, %4, %5, %6, %7, " \
        " %8, %9, %10, %11, %12, %13, %14, %15, " \
        " %16, %17, %18, %19, %20, %21, %22, %23, " \
        " %24, %25, %26, %27, %28, %29, %30, %31}, [%32];" \
        : "=r"((r)[0]),  "=r"((r)[1]),  "=r"((r)[2]),  "=r"((r)[3]), \
          "=r"((r)[4]),  "=r"((r)[5]),  "=r"((r)[6]),  "=r"((r)[7]), \
          "=r"((r)[8]),  "=r"((r)[9]),  "=r"((r)[10]), "=r"((r)[11]), \
          "=r"((r)[12]), "=r"((r)[13]), "=r"((r)[14]), "=r"((r)[15]), \
          "=r"((r)[16]), "=r"((r)[17]), "=r"((r)[18]), "=r"((r)[19]), \
          "=r"((r)[20]), "=r"((r)[21]), "=r"((r)[22]), "=r"((r)[23]), \
          "=r"((r)[24]), "=r"((r)[25]), "=r"((r)[26]), "=r"((r)[27]), \
          "=r"((r)[28]), "=r"((r)[29]), "=r"((r)[30]), "=r"((r)[31]) \
        : "r"(tmem_addr))
#endif // HAS_TC5

// ---------------- K0: init (detect + fill + zero out) ----------------
__global__ void k_init(const int* __restrict__ idx, float4* __restrict__ o) {
    long long gid = (long long)blockIdx.x * blockDim.x + threadIdx.x;
    long long st = (long long)gridDim.x * blockDim.x;
    if (blockIdx.x == 0 && threadIdx.x == 0) {
        int is64 = 1;
        for (int i = 0; i < 32; i++) {
            int lo = idx[2 * i], hi = idx[2 * i + 1];
            if (hi != 0 || lo < 0 || lo >= NEXP) { is64 = 0; break; }
        }
        g_is64 = is64;
        g_ntiles = 0;
    }
    if (gid < NEXP) g_cnt[gid] = 0;
    for (long long r = gid; r < MAXROWS; r += st) { g_pairtok[r] = 0; g_pairw[r] = 0.0f; }
    long long n4 = (long long)TNUM * DIMD / 4;
    float4 z = make_float4(0.f, 0.f, 0.f, 0.f);
    for (long long i = gid; i < n4; i += st) o[i] = z;
}

// ---------------- K1: hist-rank + all fp32->fp16 conversions ----------------
#define NX4 ((long long)TNUM * DIMD / 4)
#define NW4 ((long long)NEXP * INTERD * DIMD / 4)
__global__ void k_main(const int* __restrict__ idx,
                       const float4* __restrict__ x,  const float4* __restrict__ w1,
                       const float4* __restrict__ w3, const float4* __restrict__ w2) {
    long long gid = (long long)blockIdx.x * blockDim.x + threadIdx.x;
    long long st = (long long)gridDim.x * blockDim.x;
    if (gid < NPAIR) {
        int p = (int)gid;
        int e = g_is64 ? idx[2 * p] : idx[p];
        g_eid[p] = (uint8_t)e;
        g_rank[p] = atomicAdd(&g_cnt[e], 1);
    }
    long long total = NX4 + 3 * NW4;
    for (long long i = gid; i < total; i += st) {
        const float4* s;
        uint2* d;
        long long j;
        if (i < NX4)               { s = x;  d = (uint2*)g_xh;  j = i; }
        else if (i < NX4 + NW4)    { s = w1; d = (uint2*)g_w1h; j = i - NX4; }
        else if (i < NX4 + 2*NW4)  { s = w3; d = (uint2*)g_w3h; j = i - NX4 - NW4; }
        else                       { s = w2; d = (uint2*)g_w2h; j = i - NX4 - 2*NW4; }
        float4 v = s[j];
        __half2 a = __floats2half2_rn(v.x, v.y);
        __half2 b = __floats2half2_rn(v.z, v.w);
        uint2 ov;
        ov.x = *reinterpret_cast<uint32_t*>(&a);
        ov.y = *reinterpret_cast<uint32_t*>(&b);
        d[j] = ov;
    }
}

// ---------------- K2: plan (redundant per block) + scatter (128-row tiles) ----------
__global__ void k_planscatter(const float* __restrict__ ew) {
    __shared__ int sbase[NEXP];
    if (threadIdx.x == 0) {
        int off = 0;
        for (int e = 0; e < NEXP; e++) {
            sbase[e] = off;
            off += ((g_cnt[e] + 127) >> 7) << 7;
        }
        if (blockIdx.x == 0) {
            int nt = 0, o2 = 0;
            for (int e = 0; e < NEXP; e++) {
                int tl = (g_cnt[e] + 127) >> 7;
                for (int i = 0; i < tl; i++) { g_tile_e[nt] = e; g_tile_r0[nt] = o2 + i * 128; nt++; }
                o2 += tl << 7;
            }
            g_ntiles = nt;
        }
    }
    __syncthreads();
    for (int p = blockIdx.x * blockDim.x + threadIdx.x; p < NPAIR; p += gridDim.x * blockDim.x) {
        int e = g_eid[p];
        int pos = sbase[e] + g_rank[p];
        g_pairtok[pos] = p / TOPK;
        g_pairw[pos] = ew[p];
    }
}

__device__ __forceinline__ float silu_mul(float a, float b) {
    return (a / (1.0f + __expf(-a))) * b;
}

// Co-residency remap: classic placement maps bid and bid+NSM to the same SM.
// slot s = bid % NSM, wave w = bid / NSM; pair-group g = s + NSM*(w>>1), sub = w&1.
// Same g => co-resident pair => same (ntile, tile-pair) => same B panel (adjacent
// tiles share an expert except at boundaries). Coverage: exact, one bid per (g,sub).
#define G1TOT (NT1 * (MAXTILES / 2))     // 2600
#define G2TOT (NP2 * (MAXTILES / 2))     // 2000
#define GRID1 (NSM * 36)                 // 5328 >= 2*G1TOT, full sub coverage
#define GRID2 (NSM * 28)                 // 4144 >= 2*G2TOT

#if HAS_TC5
// ================= tcgen05 path: M=128 tiles, 2 CTAs/SM (champion config) ============

// GEMM1: h = silu(x W1^T) * (x W3^T).  CTA: M=128 x N=128.
// Buffers/chunk: A,B1,B3 (48KB). Accs: tb (W1), tb+128 (W3). 2-stage pipeline.
__global__ void __launch_bounds__(256, 2) k_gemm1() {
    int bid = blockIdx.x;
    int s0 = bid % NSM, w0 = bid / NSM;
    int g = s0 + NSM * (w0 >> 1);
    int sub = w0 & 1;
    if (g >= G1TOT) return;
    int ntile = g % NT1;
    int tile = (g / NT1) * 2 + sub;
    if (tile >= g_ntiles) return;

    extern __shared__ char dynsm[];
    __shared__ int stok[128];
    __shared__ uint32_t s_tmem[2];
    __shared__ __align__(8) unsigned long long s_mbar[2];

    int tid = threadIdx.x, wid = tid >> 5, lane = tid & 31;
    int e = g_tile_e[tile], r0 = g_tile_r0[tile];
    if (tid < 128) stok[tid] = g_pairtok[r0 + tid];

    uint32_t mb[2] = { smem_u32(&s_mbar[0]), smem_u32(&s_mbar[1]) };
    if (wid == 0) { tc_alloc(smem_u32(&s_tmem[0]), 256); tc_relinq(); }
    if (tid == 0) { mbar_init(mb[0], 1); mbar_init(mb[1], 1); }
    __syncthreads();
    uint32_t tb = s_tmem[0];
    uint32_t db = (smem_u32(dynsm) + 1023u) & ~1023u;

    const __half* B1 = g_w1h + (size_t)e * INTERD * DIMD + (size_t)ntile * 128 * DIMD;
    const __half* B3 = g_w3h + (size_t)e * INTERD * DIMD + (size_t)ntile * 128 * DIMD;

    auto load_chunk = [&](int kc, uint32_t st) {
#pragma unroll
        for (int it = 0; it < 12; it++) {
            int j2 = tid + it * 256;
            int buf = j2 >> 10, j = j2 & 1023;
            int row = j >> 3, q = j & 7;
            uint32_t dst = st + (uint32_t)buf * 16384u + SWZ((uint32_t)(row * 128 + q * 16));
            if (buf == 0)
                cpa16(dst, g_xh + (size_t)stok[row] * DIMD + kc * KC + q * 8);
            else if (buf == 1)
                cpa16ca(dst, B1 + (size_t)row * DIMD + kc * KC + q * 8);
            else
                cpa16ca(dst, B3 + (size_t)row * DIMD + kc * KC + q * 8);
        }
    };

    load_chunk(0, db);          cpa_commit();
    load_chunk(1, db + STAGEB); cpa_commit();

    int wc[2] = {0, 0};
    for (int kc = 0; kc < NK1; kc++) {
        int s = kc & 1;
        uint32_t st = db + (uint32_t)s * STAGEB;
        CPA_WAIT1();                 // chunk kc resident
        FENCE_ASYNC();
        __syncthreads();
        if (wid == 0 && elect1()) {
            uint64_t ad = MKDESC(st);
            uint64_t b1 = MKDESC(st + 16384u);
            uint64_t b3 = MKDESC(st + 32768u);
#pragma unroll
            for (int i = 0; i < 4; i++) {
                uint32_t acc = (uint32_t)((kc | i) != 0);
                mma_f16_ss(tb,       ad + i * 2, b1 + i * 2, IDESC128, acc);
                mma_f16_ss(tb + 128, ad + i * 2, b3 + i * 2, IDESC128, acc);
            }
            tc_commit(mb[s]);
        }
        if (kc + 2 < NK1) {
            mbar_wait(mb[s], wc[s] & 1);   // MMA kc done -> stage s reusable
            wc[s]++;
            load_chunk(kc + 2, st);
        }
        cpa_commit();
    }
    {
        int s = (NK1 - 1) & 1;
        mbar_wait(mb[s], wc[s] & 1);       // final commit covers all prior MMAs
    }
    tc_fence_after();

    // Epilogue, all 8 warps: sub = wid&3 -> rows sub*32..+31 (subpartition);
    // half = wid>>2 -> column range {0,1} vs {2,3}.
    {
        int half = wid >> 2, subw = wid & 3;
        int grow = r0 + subw * 32 + lane;
        __half* hrow = g_hbuf + (size_t)grow * INTERD + ntile * 128;
#pragma unroll
        for (int cc = 0; cc < 2; cc++) {
            int c = half * 2 + cc;
            uint32_t r1[32], r3[32];
            LDTM32(r1, tb + c * 32);
            LDTM32(r3, tb + 128 + c * 32);
            tc_wait_ld();
            uint4 o[4];
#pragma unroll
            for (int j = 0; j < 4; j++) {
                uint32_t p[4];
#pragma unroll
                for (int q2 = 0; q2 < 4; q2++) {
                    int i = j * 8 + q2 * 2;
                    float h0 = silu_mul(__uint_as_float(r1[i]),     __uint_as_float(r3[i]));
                    float h1 = silu_mul(__uint_as_float(r1[i + 1]), __uint_as_float(r3[i + 1]));
                    __half2 hh = __floats2half2_rn(h0, h1);
                    p[q2] = *reinterpret_cast<uint32_t*>(&hh);
                }
                o[j] = make_uint4(p[0], p[1], p[2], p[3]);
            }
            uint4* dst = (uint4*)(hrow + c * 32);
            dst[0] = o[0]; dst[1] = o[1]; dst[2] = o[2]; dst[3] = o[3];
        }
        tc_fence_before();
    }
    __syncthreads();
    if (wid == 0) tc_dealloc(tb, 256);
}

// GEMM2: y = h W2^T, scaled vector-atomic combine.  CTA: M=128 x N=256.
// Buffers/chunk: A,Blo,Bhi (48KB). Accs: tb (Nlo), tb+128 (Nhi).
__global__ void __launch_bounds__(256, 2) k_gemm2(float* __restrict__ out) {
    int bid = blockIdx.x;
    int s0 = bid % NSM, w0 = bid / NSM;
    int g = s0 + NSM * (w0 >> 1);
    int sub = w0 & 1;
    if (g >= G2TOT) return;
    int lo = (g % NP2) * 2;
    int tile = (g / NP2) * 2 + sub;
    if (tile >= g_ntiles) return;

    extern __shared__ char dynsm[];
    __shared__ uint32_t s_tmem[2];
    __shared__ __align__(8) unsigned long long s_mbar[2];

    int tid = threadIdx.x, wid = tid >> 5, lane = tid & 31;
    int e = g_tile_e[tile], r0 = g_tile_r0[tile];

    uint32_t mb[2] = { smem_u32(&s_mbar[0]), smem_u32(&s_mbar[1]) };
    if (wid == 0) { tc_alloc(smem_u32(&s_tmem[0]), 256); tc_relinq(); }
    if (tid == 0) { mbar_init(mb[0], 1); mbar_init(mb[1], 1); }
    __syncthreads();
    uint32_t tb = s_tmem[0];
    uint32_t db = (smem_u32(dynsm) + 1023u) & ~1023u;

    const __half* A  = g_hbuf + (size_t)r0 * INTERD;
    const __half* B2 = g_w2h + (size_t)e * DIMD * INTERD + (size_t)lo * 128 * INTERD;

    auto load_chunk = [&](int kc, uint32_t st) {
#pragma unroll
        for (int it = 0; it < 12; it++) {
            int j2 = tid + it * 256;
            int buf = j2 >> 10, j = j2 & 1023;
            int row = j >> 3, q = j & 7;
            uint32_t dst = st + (uint32_t)buf * 16384u + SWZ((uint32_t)(row * 128 + q * 16));
            if (buf == 0)
                cpa16(dst, A + (size_t)row * INTERD + kc * KC + q * 8);
            else if (buf == 1)
                cpa16ca(dst, B2 + (size_t)row * INTERD + kc * KC + q * 8);
            else
                cpa16ca(dst, B2 + (size_t)(128 + row) * INTERD + kc * KC + q * 8);
        }
    };

    load_chunk(0, db);          cpa_commit();
    load_chunk(1, db + STAGEB); cpa_commit();

    int wc[2] = {0, 0};
    for (int kc = 0; kc < NK2; kc++) {
        int s = kc & 1;
        uint32_t st = db + (uint32_t)s * STAGEB;
        CPA_WAIT1();
        FENCE_ASYNC();
        __syncthreads();
        if (wid == 0 && elect1()) {
            uint64_t ad  = MKDESC(st);
            uint64_t blo = MKDESC(st + 16384u);
            uint64_t bhi = MKDESC(st + 32768u);
#pragma unroll
            for (int i = 0; i < 4; i++) {
                uint32_t acc = (uint32_t)((kc | i) != 0);
                mma_f16_ss(tb,       ad + i * 2, blo + i * 2, IDESC128, acc);
                mma_f16_ss(tb + 128, ad + i * 2, bhi + i * 2, IDESC128, acc);
            }
            tc_commit(mb[s]);
        }
        if (kc + 2 < NK2) {
            mbar_wait(mb[s], wc[s] & 1);
            wc[s]++;
            load_chunk(kc + 2, st);
        }
        cpa_commit();
    }
    {
        int s = (NK2 - 1) & 1;
        mbar_wait(mb[s], wc[s] & 1);
    }
    tc_fence_after();

    // Epilogue, all 8 warps: sub = wid&3 -> rows; half = wid>>2 -> acc (Nlo/Nhi).
    {
        int half = wid >> 2, subw = wid & 3;
        int grow = r0 + subw * 32 + lane;
        float w = g_pairw[grow];
        int tok = g_pairtok[grow];
        float* orow = out + (size_t)tok * DIMD + (lo + half) * 128;
        uint32_t base = tb + (uint32_t)half * 128;
#pragma unroll
        for (int c = 0; c < 4; c++) {
            uint32_t r[32];
            LDTM32(r, base + c * 32);
            tc_wait_ld();
            if (w != 0.0f) {
#if __CUDA_ARCH__ >= 900
#pragma unroll
                for (int i = 0; i < 32; i += 4) {
                    float4 v = make_float4(w * __uint_as_float(r[i]),
                                           w * __uint_as_float(r[i + 1]),
                                           w * __uint_as_float(r[i + 2]),
                                           w * __uint_as_float(r[i + 3]));
                    atomicAdd((float4*)(orow + c * 32 + i), v);
                }
#else
#pragma unroll
                for (int i = 0; i < 32; i++)
                    atomicAdd(orow + c * 32 + i, w * __uint_as_float(r[i]));
#endif
            }
        }
        tc_fence_before();
    }
    __syncthreads();
    if (wid == 0) tc_dealloc(tb, 256);
}

#else
// ================= compile-only fallback (base-family pass; never runs on GB300) =====
__global__ void __launch_bounds__(256, 2) k_gemm1() {
    int bid = blockIdx.x;
    int s0 = bid % NSM, w0 = bid / NSM;
    int g = s0 + NSM * (w0 >> 1);
    int sub = w0 & 1;
    if (g >= G1TOT) return;
    int ntile = g % NT1;
    int tile = (g / NT1) * 2 + sub;
    if (tile >= g_ntiles) return;
    int e = g_tile_e[tile], r0 = g_tile_r0[tile];
    for (int idx = threadIdx.x; idx < 128 * 128; idx += 256) {
        int r = idx / 128, c = idx % 128;
        int grow = r0 + r, col = ntile * 128 + c;
        const __half* xr  = g_xh + (size_t)g_pairtok[grow] * DIMD;
        const __half* w1r = g_w1h + ((size_t)e * INTERD + col) * DIMD;
        const __half* w3r = g_w3h + ((size_t)e * INTERD + col) * DIMD;
        float a1 = 0.f, a3 = 0.f;
        for (int k = 0; k < DIMD; k++) {
            float xv = __half2float(xr[k]);
            a1 += xv * __half2float(w1r[k]);
            a3 += xv * __half2float(w3r[k]);
        }
        g_hbuf[(size_t)grow * INTERD + col] = __float2half_rn(silu_mul(a1, a3));
    }
}
__global__ void __launch_bounds__(256, 2) k_gemm2(float* __restrict__ out) {
    int bid = blockIdx.x;
    int s0 = bid % NSM, w0 = bid / NSM;
    int g = s0 + NSM * (w0 >> 1);
    int sub = w0 & 1;
    if (g >= G2TOT) return;
    int lo = (g % NP2) * 2;
    int tile = (g / NP2) * 2 + sub;
    if (tile >= g_ntiles) return;
    int e = g_tile_e[tile], r0 = g_tile_r0[tile];
    for (int idx = threadIdx.x; idx < 128 * 256; idx += 256) {
        int r = idx / 256, c = idx % 256;
        int grow = r0 + r, col = lo * 128 + c;
        float w = g_pairw[grow];
        if (w == 0.0f) continue;
        const __half* ar  = g_hbuf + (size_t)grow * INTERD;
        const __half* w2r = g_w2h + ((size_t)e * DIMD + col) * INTERD;
        float acc = 0.f;
        for (int k = 0; k < INTERD; k++)
            acc += __half2float(ar[k]) * __half2float(w2r[k]);
        atomicAdd(out + (size_t)g_pairtok[grow] * DIMD + col, w * acc);
    }
}
#endif // HAS_TC5

// ---------------- launch: 5 kernels; gemm1 is the 4th (profiled slot) ----------------
extern "C" void kernel_launch(void* const* d_in, const int* in_sizes, int n_in,
                              void* d_out, int out_size) {
    const float* x  = (const float*)d_in[0];
    const int*   ix = (const int*)d_in[1];
    const float* ew = (const float*)d_in[2];
    const float* w1 = (const float*)d_in[3];
    const float* w2 = (const float*)d_in[4];
    const float* w3 = (const float*)d_in[5];
    float* out = (float*)d_out;

    k_init<<<2048, 256>>>(ix, (float4*)out);
    k_main<<<4096, 256>>>(ix, (const float4*)x, (const float4*)w1,
                          (const float4*)w3, (const float4*)w2);
    k_planscatter<<<64, 256>>>(ew);

    int smem = 1024 + 2 * (int)STAGEB;   // 99328 bytes -> 2 CTAs/SM
    cudaFuncSetAttribute(k_gemm1, cudaFuncAttributeMaxDynamicSharedMemorySize, smem);
    cudaFuncSetAttribute(k_gemm2, cudaFuncAttributeMaxDynamicSharedMemorySize, smem);
    k_gemm1<<<GRID1, 256, smem>>>();
    k_gemm2<<<GRID2, 256, smem>>>(out);
}

// round 17
// speedup vs baseline: 1.4043x; 1.4043x over previous
#include <cuda_runtime.h>
#include <cuda_fp16.h>
#include <cstdint>
#include <cstddef>

// ---------------- problem constants ----------------
#define TNUM   8192
#define DIMD   2560
#define INTERD 1664
#define NEXP   16
#define TOPK   6
#define NPAIR  (TNUM * TOPK)          // 49152
#define MAXROWS 51200                 // >= 49152 + 16*127, multiple of 128
#define MAXTILES 400                  // 128-row tiles
#define KC 64                         // K elems per chunk (64 fp16 = 128B = SW128 atom row)
#define NK1 (DIMD / KC)               // 40
#define NK2 (INTERD / KC)             // 26
#define NT1 (INTERD / 128)            // 13  (N tiles of 128)
#define NP2 10                        // 20/2 ntile-pairs for GEMM2

// idesc kind::f16 (fp16 in, fp32 acc): dtype=F32(1<<4), atype=F16(0), btype=F16(0),
// N=128 -> 16<<17, M=128 -> 8<<24
#define IDESC128 0x08200010u

// Both GEMMs: 2 stages x (3 buffers x 16KB) = 48KB/stage -> 2 CTAs/SM
#define STAGEB 49152u

// Feature gate: tcgen05 is sm_103a-specific; base-family passes get a compile-only fallback.
#if defined(__CUDA_ARCH_FEAT_SM103_ALL) || (defined(__CUDA_ARCH_SPECIFIC__) && (__CUDA_ARCH_SPECIFIC__ == 1030))
#define HAS_TC5 1
#else
#define HAS_TC5 0
#endif

// ---------------- device scratch (static) ----------------
__device__ __half g_xh [(size_t)TNUM * DIMD];
__device__ __half g_w1h[(size_t)NEXP * INTERD * DIMD];
__device__ __half g_w3h[(size_t)NEXP * INTERD * DIMD];
__device__ __half g_w2h[(size_t)NEXP * DIMD * INTERD];
__device__ __half g_hbuf[(size_t)MAXROWS * INTERD];
__device__ int     g_cnt[NEXP];
__device__ int     g_rank[NPAIR];
__device__ uint8_t g_eid[NPAIR];
__device__ int   g_pairtok[MAXROWS];
__device__ float g_pairw[MAXROWS];
__device__ int   g_tile_e[MAXTILES];
__device__ int   g_tile_r0[MAXTILES];
__device__ int   g_ntiles;
__device__ int   g_is64;

// ---------------- generic helpers ----------------
__device__ __forceinline__ uint32_t smem_u32(const void* p) {
    uint32_t a;
    asm("{ .reg .u64 t; cvta.to.shared.u64 t, %1; cvt.u32.u64 %0, t; }" : "=r"(a) : "l"(p));
    return a;
}
__device__ __forceinline__ uint32_t elect1() {
    uint32_t p;
    asm volatile("{\n\t.reg .pred p;\n\telect.sync _|p, 0xFFFFFFFF;\n\tselp.b32 %0, 1, 0, p;\n\t}"
                 : "=r"(p));
    return p;
}
#define SWZ(off) ((off) ^ (((off) >> 3) & 0x70u))

__device__ __forceinline__ void mbar_init(uint32_t a, uint32_t c) {
    asm volatile("mbarrier.init.shared.b64 [%0], %1;" :: "r"(a), "r"(c) : "memory");
}
__device__ __forceinline__ void mbar_wait(uint32_t a, uint32_t parity) {
    asm volatile(
        "{\n\t.reg .pred P;\n\t"
        "W_%=:\n\t"
        "mbarrier.try_wait.parity.acquire.cta.shared::cta.b64 P, [%0], %1, 0x989680;\n\t"
        "@P bra.uni D_%=;\n\t"
        "bra.uni W_%=;\n\t"
        "D_%=:\n\t}"
        :: "r"(a), "r"(parity) : "memory");
}
__device__ __forceinline__ void cpa16(uint32_t dst, const void* src) {
    asm volatile("cp.async.cg.shared.global [%0], [%1], 16;" :: "r"(dst), "l"(src) : "memory");
}
__device__ __forceinline__ void cpa_commit() {
    asm volatile("cp.async.commit_group;" ::: "memory");
}
#define CPA_WAIT1() asm volatile("cp.async.wait_group 1;" ::: "memory")
#define FENCE_ASYNC() asm volatile("fence.proxy.async.shared::cta;" ::: "memory")

// SW128 K-major descriptor: layout=2, version=1, SBO=64, LBO=1
#define DESC_BASE ((uint64_t(2) << 61) | (uint64_t(1) << 46) | (uint64_t(64) << 32) | (uint64_t(1) << 16))
#define MKDESC(addr) (DESC_BASE | ((uint64_t)((addr) >> 4) & 0x3FFFull))

#if HAS_TC5
// ---------------- tcgen05 helpers (sm_103a-specific pass only) ----------------
__device__ __forceinline__ void tc_alloc(uint32_t smem_dst, uint32_t ncols) {
    asm volatile("tcgen05.alloc.cta_group::1.sync.aligned.shared::cta.b32 [%0], %1;"
                 :: "r"(smem_dst), "r"(ncols) : "memory");
}
__device__ __forceinline__ void tc_relinq() {
    asm volatile("tcgen05.relinquish_alloc_permit.cta_group::1.sync.aligned;");
}
__device__ __forceinline__ void tc_dealloc(uint32_t tmem, uint32_t ncols) {
    asm volatile("tcgen05.dealloc.cta_group::1.sync.aligned.b32 %0, %1;" :: "r"(tmem), "r"(ncols));
}
__device__ __forceinline__ void tc_commit(uint32_t mbar) {
    asm volatile("tcgen05.commit.cta_group::1.mbarrier::arrive::one.shared::cluster.b64 [%0];"
                 :: "r"(mbar) : "memory");
}
__device__ __forceinline__ void tc_fence_after() {
    asm volatile("tcgen05.fence::after_thread_sync;" ::: "memory");
}
__device__ __forceinline__ void tc_fence_before() {
    asm volatile("tcgen05.fence::before_thread_sync;" ::: "memory");
}
__device__ __forceinline__ void tc_wait_ld() {
    asm volatile("tcgen05.wait::ld.sync.aligned;" ::: "memory");
}
__device__ __forceinline__ void mma_f16_ss(uint32_t d, uint64_t a, uint64_t b,
                                           uint32_t idesc, uint32_t acc) {
    asm volatile(
        "{\n\t.reg .pred p;\n\tsetp.ne.u32 p, %4, 0;\n\t"
        "tcgen05.mma.cta_group::1.kind::f16 [%0], %1, %2, %3, {%5,%5,%5,%5}, p;\n\t}"
        :: "r"(d), "l"(a), "l"(b), "r"(idesc), "r"(acc), "r"(0u) : "memory");
}
#define LDTM32(r, tmem_addr) \
    asm volatile( \
        "tcgen05.ld.sync.aligned.32x32b.x32.b32 " \
        "{%0, %1, %2, %3, %4, %5, %6, %7, " \
        " %8, %9, %10, %11, %12, %13, %14, %15, " \
        " %16, %17, %18, %19, %20, %21, %22, %23, " \
        " %24, %25, %26, %27, %28, %29, %30, %31}, [%32];" \
        : "=r"((r)[0]),  "=r"((r)[1]),  "=r"((r)[2]),  "=r"((r)[3]), \
          "=r"((r)[4]),  "=r"((r)[5]),  "=r"((r)[6]),  "=r"((r)[7]), \
          "=r"((r)[8]),  "=r"((r)[9]),  "=r"((r)[10]), "=r"((r)[11]), \
          "=r"((r)[12]), "=r"((r)[13]), "=r"((r)[14]), "=r"((r)[15]), \
          "=r"((r)[16]), "=r"((r)[17]), "=r"((r)[18]), "=r"((r)[19]), \
          "=r"((r)[20]), "=r"((r)[21]), "=r"((r)[22]), "=r"((r)[23]), \
          "=r"((r)[24]), "=r"((r)[25]), "=r"((r)[26]), "=r"((r)[27]), \
          "=r"((r)[28]), "=r"((r)[29]), "=r"((r)[30]), "=r"((r)[31]) \
        : "r"(tmem_addr))
#endif // HAS_TC5

// ---------------- K0: init (detect + fill + zero out) ----------------
__global__ void k_init(const int* __restrict__ idx, float4* __restrict__ o) {
    long long gid = (long long)blockIdx.x * blockDim.x + threadIdx.x;
    long long st = (long long)gridDim.x * blockDim.x;
    if (blockIdx.x == 0 && threadIdx.x == 0) {
        int is64 = 1;
        for (int i = 0; i < 32; i++) {
            int lo = idx[2 * i], hi = idx[2 * i + 1];
            if (hi != 0 || lo < 0 || lo >= NEXP) { is64 = 0; break; }
        }
        g_is64 = is64;
        g_ntiles = 0;
    }
    if (gid < NEXP) g_cnt[gid] = 0;
    for (long long r = gid; r < MAXROWS; r += st) { g_pairtok[r] = 0; g_pairw[r] = 0.0f; }
    long long n4 = (long long)TNUM * DIMD / 4;
    float4 z = make_float4(0.f, 0.f, 0.f, 0.f);
    for (long long i = gid; i < n4; i += st) o[i] = z;
}

// ---------------- K1: hist-rank + all fp32->fp16 conversions ----------------
#define NX4 ((long long)TNUM * DIMD / 4)
#define NW4 ((long long)NEXP * INTERD * DIMD / 4)
__global__ void k_main(const int* __restrict__ idx,
                       const float4* __restrict__ x,  const float4* __restrict__ w1,
                       const float4* __restrict__ w3, const float4* __restrict__ w2) {
    long long gid = (long long)blockIdx.x * blockDim.x + threadIdx.x;
    long long st = (long long)gridDim.x * blockDim.x;
    if (gid < NPAIR) {
        int p = (int)gid;
        int e = g_is64 ? idx[2 * p] : idx[p];
        g_eid[p] = (uint8_t)e;
        g_rank[p] = atomicAdd(&g_cnt[e], 1);
    }
    long long total = NX4 + 3 * NW4;
    for (long long i = gid; i < total; i += st) {
        const float4* s;
        uint2* d;
        long long j;
        if (i < NX4)               { s = x;  d = (uint2*)g_xh;  j = i; }
        else if (i < NX4 + NW4)    { s = w1; d = (uint2*)g_w1h; j = i - NX4; }
        else if (i < NX4 + 2*NW4)  { s = w3; d = (uint2*)g_w3h; j = i - NX4 - NW4; }
        else                       { s = w2; d = (uint2*)g_w2h; j = i - NX4 - 2*NW4; }
        float4 v = s[j];
        __half2 a = __floats2half2_rn(v.x, v.y);
        __half2 b = __floats2half2_rn(v.z, v.w);
        uint2 ov;
        ov.x = *reinterpret_cast<uint32_t*>(&a);
        ov.y = *reinterpret_cast<uint32_t*>(&b);
        d[j] = ov;
    }
}

// ---------------- K2: plan (redundant per block) + scatter (128-row tiles) ----------
__global__ void k_planscatter(const float* __restrict__ ew) {
    __shared__ int sbase[NEXP];
    if (threadIdx.x == 0) {
        int off = 0;
        for (int e = 0; e < NEXP; e++) {
            sbase[e] = off;
            off += ((g_cnt[e] + 127) >> 7) << 7;
        }
        if (blockIdx.x == 0) {
            int nt = 0, o2 = 0;
            for (int e = 0; e < NEXP; e++) {
                int tl = (g_cnt[e] + 127) >> 7;
                for (int i = 0; i < tl; i++) { g_tile_e[nt] = e; g_tile_r0[nt] = o2 + i * 128; nt++; }
                o2 += tl << 7;
            }
            g_ntiles = nt;
        }
    }
    __syncthreads();
    for (int p = blockIdx.x * blockDim.x + threadIdx.x; p < NPAIR; p += gridDim.x * blockDim.x) {
        int e = g_eid[p];
        int pos = sbase[e] + g_rank[p];
        g_pairtok[pos] = p / TOPK;
        g_pairw[pos] = ew[p];
    }
}

__device__ __forceinline__ float silu_mul(float a, float b) {
    return (a / (1.0f + __expf(-a))) * b;
}

#if HAS_TC5
// ================= tcgen05 path: M=128 tiles, 2 CTAs/SM (champion config) ============

// GEMM1: h = silu(x W1^T) * (x W3^T).  CTA: M=128 x N=128.
// Buffers/chunk: A,B1,B3 (48KB). Accs: tb (W1), tb+128 (W3). 2-stage pipeline.
__global__ void __launch_bounds__(256, 2) k_gemm1() {
    int tile = blockIdx.y;
    if (tile >= g_ntiles) return;
    int ntile = blockIdx.x;

    extern __shared__ char dynsm[];
    __shared__ int stok[128];
    __shared__ uint32_t s_tmem[2];
    __shared__ __align__(8) unsigned long long s_mbar[2];

    int tid = threadIdx.x, wid = tid >> 5, lane = tid & 31;
    int e = g_tile_e[tile], r0 = g_tile_r0[tile];
    if (tid < 128) stok[tid] = g_pairtok[r0 + tid];

    uint32_t mb[2] = { smem_u32(&s_mbar[0]), smem_u32(&s_mbar[1]) };
    if (wid == 0) { tc_alloc(smem_u32(&s_tmem[0]), 256); tc_relinq(); }
    if (tid == 0) { mbar_init(mb[0], 1); mbar_init(mb[1], 1); }
    __syncthreads();
    uint32_t tb = s_tmem[0];
    uint32_t db = (smem_u32(dynsm) + 1023u) & ~1023u;

    const __half* B1 = g_w1h + (size_t)e * INTERD * DIMD + (size_t)ntile * 128 * DIMD;
    const __half* B3 = g_w3h + (size_t)e * INTERD * DIMD + (size_t)ntile * 128 * DIMD;

    auto load_chunk = [&](int kc, uint32_t st) {
#pragma unroll
        for (int it = 0; it < 12; it++) {
            int j2 = tid + it * 256;
            int buf = j2 >> 10, j = j2 & 1023;
            int row = j >> 3, q = j & 7;
            const __half* src;
            if      (buf == 0) src = g_xh + (size_t)stok[row] * DIMD + kc * KC + q * 8;
            else if (buf == 1) src = B1 + (size_t)row * DIMD + kc * KC + q * 8;
            else               src = B3 + (size_t)row * DIMD + kc * KC + q * 8;
            cpa16(st + (uint32_t)buf * 16384u + SWZ((uint32_t)(row * 128 + q * 16)), src);
        }
    };

    load_chunk(0, db);          cpa_commit();
    load_chunk(1, db + STAGEB); cpa_commit();

    int wc[2] = {0, 0};
    for (int kc = 0; kc < NK1; kc++) {
        int s = kc & 1;
        uint32_t st = db + (uint32_t)s * STAGEB;
        CPA_WAIT1();                 // chunk kc resident
        FENCE_ASYNC();
        __syncthreads();
        if (wid == 0 && elect1()) {
            uint64_t ad = MKDESC(st);
            uint64_t b1 = MKDESC(st + 16384u);
            uint64_t b3 = MKDESC(st + 32768u);
#pragma unroll
            for (int i = 0; i < 4; i++) {
                uint32_t acc = (uint32_t)((kc | i) != 0);
                mma_f16_ss(tb,       ad + i * 2, b1 + i * 2, IDESC128, acc);
                mma_f16_ss(tb + 128, ad + i * 2, b3 + i * 2, IDESC128, acc);
            }
            tc_commit(mb[s]);
        }
        if (kc + 2 < NK1) {
            mbar_wait(mb[s], wc[s] & 1);   // MMA kc done -> stage s reusable
            wc[s]++;
            load_chunk(kc + 2, st);
        }
        cpa_commit();
    }
    {
        int s = (NK1 - 1) & 1;
        mbar_wait(mb[s], wc[s] & 1);       // final commit covers all prior MMAs
    }
    tc_fence_after();

    // Epilogue, all 8 warps: sub = wid&3 -> rows sub*32..+31 (subpartition);
    // half = wid>>2 -> column range {0,1} vs {2,3}.
    {
        int half = wid >> 2, sub = wid & 3;
        int grow = r0 + sub * 32 + lane;
        __half* hrow = g_hbuf + (size_t)grow * INTERD + ntile * 128;
#pragma unroll
        for (int cc = 0; cc < 2; cc++) {
            int c = half * 2 + cc;
            uint32_t r1[32], r3[32];
            LDTM32(r1, tb + c * 32);
            LDTM32(r3, tb + 128 + c * 32);
            tc_wait_ld();
            uint4 o[4];
#pragma unroll
            for (int j = 0; j < 4; j++) {
                uint32_t p[4];
#pragma unroll
                for (int q2 = 0; q2 < 4; q2++) {
                    int i = j * 8 + q2 * 2;
                    float h0 = silu_mul(__uint_as_float(r1[i]),     __uint_as_float(r3[i]));
                    float h1 = silu_mul(__uint_as_float(r1[i + 1]), __uint_as_float(r3[i + 1]));
                    __half2 hh = __floats2half2_rn(h0, h1);
                    p[q2] = *reinterpret_cast<uint32_t*>(&hh);
                }
                o[j] = make_uint4(p[0], p[1], p[2], p[3]);
            }
            uint4* dst = (uint4*)(hrow + c * 32);
            dst[0] = o[0]; dst[1] = o[1]; dst[2] = o[2]; dst[3] = o[3];
        }
        tc_fence_before();
    }
    __syncthreads();
    if (wid == 0) tc_dealloc(tb, 256);
}

// GEMM2: y = h W2^T, scaled vector-atomic combine.  CTA: M=128 x N=256.
// Buffers/chunk: A,Blo,Bhi (48KB). Accs: tb (Nlo), tb+128 (Nhi).
__global__ void __launch_bounds__(256, 2) k_gemm2(float* __restrict__ out) {
    int tile = blockIdx.y;
    if (tile >= g_ntiles) return;
    int lo = blockIdx.x * 2;

    extern __shared__ char dynsm[];
    __shared__ uint32_t s_tmem[2];
    __shared__ __align__(8) unsigned long long s_mbar[2];

    int tid = threadIdx.x, wid = tid >> 5, lane = tid & 31;
    int e = g_tile_e[tile], r0 = g_tile_r0[tile];

    uint32_t mb[2] = { smem_u32(&s_mbar[0]), smem_u32(&s_mbar[1]) };
    if (wid == 0) { tc_alloc(smem_u32(&s_tmem[0]), 256); tc_relinq(); }
    if (tid == 0) { mbar_init(mb[0], 1); mbar_init(mb[1], 1); }
    __syncthreads();
    uint32_t tb = s_tmem[0];
    uint32_t db = (smem_u32(dynsm) + 1023u) & ~1023u;

    const __half* A  = g_hbuf + (size_t)r0 * INTERD;
    const __half* B2 = g_w2h + (size_t)e * DIMD * INTERD + (size_t)lo * 128 * INTERD;

    auto load_chunk = [&](int kc, uint32_t st) {
#pragma unroll
        for (int it = 0; it < 12; it++) {
            int j2 = tid + it * 256;
            int buf = j2 >> 10, j = j2 & 1023;
            int row = j >> 3, q = j & 7;
            const __half* src;
            if      (buf == 0) src = A  + (size_t)row * INTERD + kc * KC + q * 8;
            else if (buf == 1) src = B2 + (size_t)row * INTERD + kc * KC + q * 8;
            else               src = B2 + (size_t)(128 + row) * INTERD + kc * KC + q * 8;
            cpa16(st + (uint32_t)buf * 16384u + SWZ((uint32_t)(row * 128 + q * 16)), src);
        }
    };

    load_chunk(0, db);          cpa_commit();
    load_chunk(1, db + STAGEB); cpa_commit();

    int wc[2] = {0, 0};
    for (int kc = 0; kc < NK2; kc++) {
        int s = kc & 1;
        uint32_t st = db + (uint32_t)s * STAGEB;
        CPA_WAIT1();
        FENCE_ASYNC();
        __syncthreads();
        if (wid == 0 && elect1()) {
            uint64_t ad  = MKDESC(st);
            uint64_t blo = MKDESC(st + 16384u);
            uint64_t bhi = MKDESC(st + 32768u);
#pragma unroll
            for (int i = 0; i < 4; i++) {
                uint32_t acc = (uint32_t)((kc | i) != 0);
                mma_f16_ss(tb,       ad + i * 2, blo + i * 2, IDESC128, acc);
                mma_f16_ss(tb + 128, ad + i * 2, bhi + i * 2, IDESC128, acc);
            }
            tc_commit(mb[s]);
        }
        if (kc + 2 < NK2) {
            mbar_wait(mb[s], wc[s] & 1);
            wc[s]++;
            load_chunk(kc + 2, st);
        }
        cpa_commit();
    }
    {
        int s = (NK2 - 1) & 1;
        mbar_wait(mb[s], wc[s] & 1);
    }
    tc_fence_after();

    // Epilogue, all 8 warps: sub = wid&3 -> rows; half = wid>>2 -> acc (Nlo/Nhi).
    {
        int half = wid >> 2, sub = wid & 3;
        int grow = r0 + sub * 32 + lane;
        float w = g_pairw[grow];
        int tok = g_pairtok[grow];
        float* orow = out + (size_t)tok * DIMD + (lo + half) * 128;
        uint32_t base = tb + (uint32_t)half * 128;
#pragma unroll
        for (int c = 0; c < 4; c++) {
            uint32_t r[32];
            LDTM32(r, base + c * 32);
            tc_wait_ld();
            if (w != 0.0f) {
#if __CUDA_ARCH__ >= 900
#pragma unroll
                for (int i = 0; i < 32; i += 4) {
                    float4 v = make_float4(w * __uint_as_float(r[i]),
                                           w * __uint_as_float(r[i + 1]),
                                           w * __uint_as_float(r[i + 2]),
                                           w * __uint_as_float(r[i + 3]));
                    atomicAdd((float4*)(orow + c * 32 + i), v);
                }
#else
#pragma unroll
                for (int i = 0; i < 32; i++)
                    atomicAdd(orow + c * 32 + i, w * __uint_as_float(r[i]));
#endif
            }
        }
        tc_fence_before();
    }
    __syncthreads();
    if (wid == 0) tc_dealloc(tb, 256);
}

#else
// ================= compile-only fallback (base-family pass; never runs on GB300) =====
__global__ void __launch_bounds__(256, 2) k_gemm1() {
    int tile = blockIdx.y;
    if (tile >= g_ntiles) return;
    int ntile = blockIdx.x;
    int e = g_tile_e[tile], r0 = g_tile_r0[tile];
    for (int idx = threadIdx.x; idx < 128 * 128; idx += 256) {
        int r = idx / 128, c = idx % 128;
        int grow = r0 + r, col = ntile * 128 + c;
        const __half* xr  = g_xh + (size_t)g_pairtok[grow] * DIMD;
        const __half* w1r = g_w1h + ((size_t)e * INTERD + col) * DIMD;
        const __half* w3r = g_w3h + ((size_t)e * INTERD + col) * DIMD;
        float a1 = 0.f, a3 = 0.f;
        for (int k = 0; k < DIMD; k++) {
            float xv = __half2float(xr[k]);
            a1 += xv * __half2float(w1r[k]);
            a3 += xv * __half2float(w3r[k]);
        }
        g_hbuf[(size_t)grow * INTERD + col] = __float2half_rn(silu_mul(a1, a3));
    }
}
__global__ void __launch_bounds__(256, 2) k_gemm2(float* __restrict__ out) {
    int tile = blockIdx.y;
    if (tile >= g_ntiles) return;
    int lo = blockIdx.x * 2;
    int e = g_tile_e[tile], r0 = g_tile_r0[tile];
    for (int idx = threadIdx.x; idx < 128 * 256; idx += 256) {
        int r = idx / 256, c = idx % 256;
        int grow = r0 + r, col = lo * 128 + c;
        float w = g_pairw[grow];
        if (w == 0.0f) continue;
        const __half* ar  = g_hbuf + (size_t)grow * INTERD;
        const __half* w2r = g_w2h + ((size_t)e * DIMD + col) * INTERD;
        float acc = 0.f;
        for (int k = 0; k < INTERD; k++)
            acc += __half2float(ar[k]) * __half2float(w2r[k]);
        atomicAdd(out + (size_t)g_pairtok[grow] * DIMD + col, w * acc);
    }
}
#endif // HAS_TC5

// ---------------- launch: 5 kernels; gemm1 is the 4th (profiled slot) ----------------
extern "C" void kernel_launch(void* const* d_in, const int* in_sizes, int n_in,
                              void* d_out, int out_size) {
    const float* x  = (const float*)d_in[0];
    const int*   ix = (const int*)d_in[1];
    const float* ew = (const float*)d_in[2];
    const float* w1 = (const float*)d_in[3];
    const float* w2 = (const float*)d_in[4];
    const float* w3 = (const float*)d_in[5];
    float* out = (float*)d_out;

    k_init<<<2048, 256>>>(ix, (float4*)out);
    k_main<<<4096, 256>>>(ix, (const float4*)x, (const float4*)w1,
                          (const float4*)w3, (const float4*)w2);
    k_planscatter<<<64, 256>>>(ew);

    int smem = 1024 + 2 * (int)STAGEB;   // 99328 bytes -> 2 CTAs/SM
    cudaFuncSetAttribute(k_gemm1, cudaFuncAttributeMaxDynamicSharedMemorySize, smem);
    cudaFuncSetAttribute(k_gemm2, cudaFuncAttributeMaxDynamicSharedMemorySize, smem);
    k_gemm1<<<dim3(NT1, MAXTILES), 256, smem>>>();
    k_gemm2<<<dim3(NP2, MAXTILES), 256, smem>>>(out);
}